// round 17
// baseline (speedup 1.0000x reference)
#include <cuda_runtime.h>
#include <math.h>
#include <stdint.h>

#define BSZ  256
#define TLEN 256
#define NINV 128
#define HV   256
#define GV   768   // 3H
#define H2V  512   // 2H

// ---------------- device scratch ----------------
// whh fragments for scan (bf16x3 path): [96 nt][16 ks][32 lanes] uint4
__device__ uint4 g_fH1f[96 * 16 * 32];
__device__ uint4 g_fH1r[96 * 16 * 32];
__device__ uint4 g_fH2f[96 * 16 * 32];
__device__ uint4 g_fH2r[96 * 16 * 32];
// wih bf16 hi fragments: [96 nt][K/16][32] uint2 {bh0,bh1}
__device__ uint2 g_fWbf1f[96 * 8 * 32];
__device__ uint2 g_fWbf1r[96 * 8 * 32];
__device__ uint2 g_fWbf2f[96 * 32 * 32];
__device__ uint2 g_fWbf2r[96 * 32 * 32];
// wih fp8 fragments: [96 nt][K/32][32] uint4 {bh8_0,bh8_1,bl8_0,bl8_1}
__device__ uint4 g_fW8_1f[96 * 4 * 32];
__device__ uint4 g_fW8_1r[96 * 4 * 32];
__device__ uint4 g_fW8_2f[96 * 16 * 32];
__device__ uint4 g_fW8_2r[96 * 16 * 32];
__device__ float g_bihP[4][GV];
__device__ float g_bhhP[4][GV];
__device__ float g_xgf[(size_t)TLEN * BSZ * GV];
__device__ float g_xgr[(size_t)TLEN * BSZ * GV];
__device__ uint32_t g_xinhi[(size_t)BSZ * TLEN * (NINV / 2)];   // input bf16-hi pairs
__device__ uint8_t g_xh8[(size_t)BSZ * TLEN * NINV];            // e4m3(x)
__device__ uint8_t g_xl8[(size_t)BSZ * TLEN * NINV];            // e4m3((x-hi)*256)
__device__ uint32_t g_r1hi[(size_t)BSZ * TLEN * (H2V / 2)];     // rec1 bf16-hi pairs
__device__ uint8_t g_r1h8[(size_t)BSZ * TLEN * H2V];
__device__ uint8_t g_r1l8[(size_t)BSZ * TLEN * H2V];
__device__ float g_rec2[(size_t)BSZ * TLEN * H2V];
__device__ uint32_t g_hshi[2][2][BSZ * (HV / 2)];   // split h state (scan)
__device__ uint32_t g_hslo[2][2][BSZ * (HV / 2)];
__device__ unsigned g_gcnt[16 * 32];
__device__ volatile unsigned g_ggen[16 * 32];

// Packed column c = jt*96 + gate*32 + jl  <->  orig row = gate*256 + jt*32 + jl
__device__ __forceinline__ int orig_row(int c) {
    int g = (c % 96) >> 5;
    int jt = c / 96;
    int jl = c & 31;
    return g * HV + jt * 32 + jl;
}

// ---------------- bf16 / fp8 helpers ----------------
__device__ __forceinline__ uint16_t bf16_rn(float x) {
    uint16_t u;
    asm("cvt.rn.bf16.f32 %0, %1;" : "=h"(u) : "f"(x));
    return u;
}
__device__ __forceinline__ void split2pack(float a, float b, uint32_t& hw, uint32_t& lw) {
    uint16_t ha = bf16_rn(a);
    float hfa = __uint_as_float((uint32_t)ha << 16);
    uint16_t la = bf16_rn(a - hfa);
    uint16_t hb = bf16_rn(b);
    float hfb = __uint_as_float((uint32_t)hb << 16);
    uint16_t lb = bf16_rn(b - hfb);
    hw = (uint32_t)ha | ((uint32_t)hb << 16);
    lw = (uint32_t)la | ((uint32_t)lb << 16);
}
// packs {hi_elem -> high byte, lo_elem -> low byte}
__device__ __forceinline__ uint16_t e4m3x2(float hi_elem, float lo_elem) {
    uint16_t u;
    asm("cvt.rn.satfinite.e4m3x2.f32 %0, %1, %2;" : "=h"(u) : "f"(hi_elem), "f"(lo_elem));
    return u;
}
__device__ __forceinline__ uint32_t pack4_e4m3(float v0, float v1, float v2, float v3) {
    uint16_t lo = e4m3x2(v1, v0);
    uint16_t hi = e4m3x2(v3, v2);
    return (uint32_t)lo | ((uint32_t)hi << 16);
}
__device__ __forceinline__ uint32_t smem_u32(const void* p) {
    return (uint32_t)__cvta_generic_to_shared(p);
}
__device__ __forceinline__ void ldm4(uint32_t* a, uint32_t addr) {
    asm volatile("ldmatrix.sync.aligned.m8n8.x4.shared.b16 {%0,%1,%2,%3}, [%4];"
                 : "=r"(a[0]), "=r"(a[1]), "=r"(a[2]), "=r"(a[3]) : "r"(addr));
}
__device__ __forceinline__ void mma16(float* c, const uint32_t* a, uint32_t b0, uint32_t b1) {
    asm volatile("mma.sync.aligned.m16n8k16.row.col.f32.bf16.bf16.f32 "
                 "{%0,%1,%2,%3},{%4,%5,%6,%7},{%8,%9},{%0,%1,%2,%3};"
                 : "+f"(c[0]), "+f"(c[1]), "+f"(c[2]), "+f"(c[3])
                 : "r"(a[0]), "r"(a[1]), "r"(a[2]), "r"(a[3]), "r"(b0), "r"(b1));
}
__device__ __forceinline__ void mma32f8(float* c, const uint32_t* a, uint32_t b0, uint32_t b1) {
    asm volatile("mma.sync.aligned.m16n8k32.row.col.f32.e4m3.e4m3.f32 "
                 "{%0,%1,%2,%3},{%4,%5,%6,%7},{%8,%9},{%0,%1,%2,%3};"
                 : "+f"(c[0]), "+f"(c[1]), "+f"(c[2]), "+f"(c[3])
                 : "r"(a[0]), "r"(a[1]), "r"(a[2]), "r"(a[3]), "r"(b0), "r"(b1));
}
__device__ __forceinline__ float sigm(float x) {
    float e = __expf(-x);
    return __fdividef(1.0f, 1.0f + e);
}
__device__ __forceinline__ void cpa16(uint32_t dst, const void* src) {
    asm volatile("cp.async.cg.shared.global [%0], [%1], 16;" :: "r"(dst), "l"(src));
}
#define CP_COMMIT() asm volatile("cp.async.commit_group;" ::: "memory")
#define CP_WAIT0()  asm volatile("cp.async.wait_group 0;" ::: "memory")
#define CP_WAIT1()  asm volatile("cp.async.wait_group 1;" ::: "memory")

// ---------------- packing ----------------
// whh fragments (hi+lo bf16) for the scan — unchanged
__global__ void pack_frag(uint4* __restrict__ dst, const float* __restrict__ src, int Din) {
    int KS = Din >> 4;
    int tot = 96 * KS * 32;
    for (int idx = blockIdx.x * blockDim.x + threadIdx.x; idx < tot;
         idx += gridDim.x * blockDim.x) {
        int lane = idx & 31;
        int ks = (idx >> 5) % KS;
        int nt = idx / (32 * KS);
        int cg = nt * 8 + (lane >> 2);
        int r = orig_row(cg);
        int k0 = ks * 16 + (lane & 3) * 2;
        const float* s = src + (size_t)r * Din;
        uint32_t bh0, bl0, bh1, bl1;
        split2pack(s[k0], s[k0 + 1], bh0, bl0);
        split2pack(s[k0 + 8], s[k0 + 9], bh1, bl1);
        dst[idx] = make_uint4(bh0, bh1, bl0, bl1);
    }
}

// wih bf16 hi fragments only
__global__ void pack_fragbf(uint2* __restrict__ dst, const float* __restrict__ src, int Din) {
    int KS = Din >> 4;
    int tot = 96 * KS * 32;
    for (int idx = blockIdx.x * blockDim.x + threadIdx.x; idx < tot;
         idx += gridDim.x * blockDim.x) {
        int lane = idx & 31;
        int ks = (idx >> 5) % KS;
        int nt = idx / (32 * KS);
        int cg = nt * 8 + (lane >> 2);
        int r = orig_row(cg);
        int k0 = ks * 16 + (lane & 3) * 2;
        const float* s = src + (size_t)r * Din;
        uint32_t bh0 = (uint32_t)bf16_rn(s[k0]) | ((uint32_t)bf16_rn(s[k0 + 1]) << 16);
        uint32_t bh1 = (uint32_t)bf16_rn(s[k0 + 8]) | ((uint32_t)bf16_rn(s[k0 + 9]) << 16);
        dst[idx] = make_uint2(bh0, bh1);
    }
}

// wih fp8 fragments: {e4m3(w) k0..k0+3, k0+16..+19, e4m3((w-hi)*256) same}
__global__ void pack_frag8(uint4* __restrict__ dst, const float* __restrict__ src, int Din) {
    int KS32 = Din >> 5;
    int tot = 96 * KS32 * 32;
    for (int idx = blockIdx.x * blockDim.x + threadIdx.x; idx < tot;
         idx += gridDim.x * blockDim.x) {
        int lane = idx & 31;
        int ks = (idx >> 5) % KS32;
        int nt = idx / (32 * KS32);
        int cg = nt * 8 + (lane >> 2);
        int r = orig_row(cg);
        int k0 = ks * 32 + (lane & 3) * 4;
        const float* s = src + (size_t)r * Din;
        float h[8], l[8];
#pragma unroll
        for (int j = 0; j < 4; j++) {
            float v = s[k0 + j];
            float hi = __uint_as_float((uint32_t)bf16_rn(v) << 16);
            h[j] = v; l[j] = (v - hi) * 256.0f;
            float v2 = s[k0 + 16 + j];
            float hi2 = __uint_as_float((uint32_t)bf16_rn(v2) << 16);
            h[4 + j] = v2; l[4 + j] = (v2 - hi2) * 256.0f;
        }
        dst[idx] = make_uint4(pack4_e4m3(h[0], h[1], h[2], h[3]),
                              pack4_e4m3(h[4], h[5], h[6], h[7]),
                              pack4_e4m3(l[0], l[1], l[2], l[3]),
                              pack4_e4m3(l[4], l[5], l[6], l[7]));
    }
}

__global__ void pack_b(float* __restrict__ dst, const float* __restrict__ src) {
    int c = threadIdx.x;
    if (c < GV) dst[c] = src[orig_row(c)];
}

__global__ void zero_h() {
    int idx = blockIdx.x * blockDim.x + threadIdx.x;
    int stride = gridDim.x * blockDim.x;
    for (int i = idx; i < 2 * BSZ * (HV / 2); i += stride) {
        ((uint32_t*)g_hshi)[i] = 0u;
        ((uint32_t*)g_hslo)[i] = 0u;
    }
}

// input fp32 -> bf16-hi word pairs + fp8 hi/lo bytes
__global__ void split_input(const float* __restrict__ src, uint32_t* __restrict__ hi,
                            uint8_t* __restrict__ h8, uint8_t* __restrict__ l8, int words) {
    for (int idx = blockIdx.x * blockDim.x + threadIdx.x; idx < words;
         idx += gridDim.x * blockDim.x) {
        float2 v = *(const float2*)&src[(size_t)idx * 2];
        uint16_t ha = bf16_rn(v.x), hb = bf16_rn(v.y);
        hi[idx] = (uint32_t)ha | ((uint32_t)hb << 16);
        float la = (v.x - __uint_as_float((uint32_t)ha << 16)) * 256.0f;
        float lb = (v.y - __uint_as_float((uint32_t)hb << 16)) * 256.0f;
        *(uint16_t*)&h8[(size_t)idx * 2] = e4m3x2(v.y, v.x);
        *(uint16_t*)&l8[(size_t)idx * 2] = e4m3x2(lb, la);
    }
}

// ---------------- input-gate GEMM (bf16 hh + e4m3 corrections) ----------------
// Stage layout: AH 0 (64x144=9216), A8H 9216 (64x80=5120), A8L 14336 (5120),
//               BBF 19456 (8192), B8 27648 (8192). Stage = 35840.
#define XG_STAGE 35840
#define XG_SMEM (2 * XG_STAGE)
#define A8H_OFF 9216
#define A8L_OFF 14336
#define BBF_OFF 19456
#define B8_OFF 27648
extern __shared__ char smem_raw[];

template <int KW>   // bf16-hi words per A row (K/2); K bytes = KW*2
__device__ __forceinline__ void xg_issue(uint32_t st, int tid, int m0, int n0blk, int ch,
                                         const uint32_t* __restrict__ Ahi,
                                         const uint8_t* __restrict__ A8h,
                                         const uint8_t* __restrict__ A8l,
                                         const uint2* __restrict__ fBbf,
                                         const uint4* __restrict__ fB8) {
    const int KS16 = KW >> 3;
    const int KS32 = KW >> 4;
    const int KB = KW * 2;
    int kcW = ch * 32;
    int kcB = ch * 64;
    for (int idx = tid; idx < 2048; idx += 128) {
        if (idx < 512) {            // A bf16 hi: 64 rows x 8 x 16B
            int row = idx >> 3, q = idx & 7;
            cpa16(st + row * 144 + q * 16, &Ahi[(size_t)(m0 + row) * KW + kcW + q * 4]);
        } else if (idx < 768) {     // A8h: 64 rows x 4 x 16B
            int e = idx - 512, row = e >> 2, q = e & 3;
            cpa16(st + A8H_OFF + row * 80 + q * 16,
                  &A8h[(size_t)(m0 + row) * KB + kcB + q * 16]);
        } else if (idx < 1024) {    // A8l
            int e = idx - 768, row = e >> 2, q = e & 3;
            cpa16(st + A8L_OFF + row * 80 + q * 16,
                  &A8l[(size_t)(m0 + row) * KB + kcB + q * 16]);
        } else if (idx < 1536) {    // B bf16 frags: 8 nt x 1024B
            int e = idx - 1024;
            int nt = e >> 6, rest = e & 63;
            const char* src = (const char*)&fBbf[((size_t)(n0blk + nt) * KS16 + ch * 4) * 32];
            cpa16(st + BBF_OFF + nt * 1024 + rest * 16, src + rest * 16);
        } else {                    // B fp8 frags: 8 nt x 1024B
            int e = idx - 1536;
            int nt = e >> 6, rest = e & 63;
            const char* src = (const char*)&fB8[((size_t)(n0blk + nt) * KS32 + ch * 2) * 32];
            cpa16(st + B8_OFF + nt * 1024 + rest * 16, src + rest * 16);
        }
    }
    CP_COMMIT();
}

template <int KW>
__global__ void __launch_bounds__(128) xg_mma(const uint32_t* __restrict__ Ahi,
                                              const uint8_t* __restrict__ A8h,
                                              const uint8_t* __restrict__ A8l,
                                              const uint2* __restrict__ fBbf,
                                              const uint4* __restrict__ fB8,
                                              const float* __restrict__ bias,
                                              float* __restrict__ out) {
    const int NC = KW / 32;
    uint32_t sb = smem_u32(smem_raw);
    int tid = threadIdx.x;
    int w = tid >> 5, lane = tid & 31;
    int m0 = blockIdx.y * 64;
    int n0blk = blockIdx.x * 8;
    int wm = (w & 1) * 32;
    int wn = (w >> 1) * 4;
    int r = lane >> 2, cc = lane & 3;
    int rl = lane & 15, kh = (lane >> 4) * 16;
    int r4 = lane >> 2, c4 = (lane & 3) * 4;

    xg_issue<KW>(sb, tid, m0, n0blk, 0, Ahi, A8h, A8l, fBbf, fB8);

    float acc[2][4][4] = {};
    float accc[2][4][4] = {};
    for (int ch = 0; ch < NC; ch++) {
        int s = ch & 1;
        if (ch + 1 < NC) {
            xg_issue<KW>(sb + (s ^ 1) * XG_STAGE, tid, m0, n0blk, ch + 1,
                         Ahi, A8h, A8l, fBbf, fB8);
            CP_WAIT1();
        } else {
            CP_WAIT0();
        }
        __syncthreads();
        uint32_t stg = sb + s * XG_STAGE;
        uint32_t aH = stg + (wm + rl) * 144 + kh;
        const char* p8h = smem_raw + s * XG_STAGE + A8H_OFF;
        const char* p8l = smem_raw + s * XG_STAGE + A8L_OFF;
        const uint2* sBbf = (const uint2*)(smem_raw + s * XG_STAGE + BBF_OFF);
        const uint4* sB8v = (const uint4*)(smem_raw + s * XG_STAGE + B8_OFF);
#pragma unroll
        for (int ks32 = 0; ks32 < 2; ks32++) {
            uint32_t ahA0[4], ahA1[4], ahB0[4], ahB1[4];
            ldm4(ahA0, aH + (2 * ks32) * 32);
            ldm4(ahA1, aH + 16 * 144 + (2 * ks32) * 32);
            ldm4(ahB0, aH + (2 * ks32 + 1) * 32);
            ldm4(ahB1, aH + 16 * 144 + (2 * ks32 + 1) * 32);
            int kb = ks32 * 32 + c4;
            uint32_t a8h0[4], a8h1[4], a8l0[4], a8l1[4];
            int row0 = wm + r4;
            a8h0[0] = *(const uint32_t*)(p8h + row0 * 80 + kb);
            a8h0[1] = *(const uint32_t*)(p8h + (row0 + 8) * 80 + kb);
            a8h0[2] = *(const uint32_t*)(p8h + row0 * 80 + kb + 16);
            a8h0[3] = *(const uint32_t*)(p8h + (row0 + 8) * 80 + kb + 16);
            a8h1[0] = *(const uint32_t*)(p8h + (row0 + 16) * 80 + kb);
            a8h1[1] = *(const uint32_t*)(p8h + (row0 + 24) * 80 + kb);
            a8h1[2] = *(const uint32_t*)(p8h + (row0 + 16) * 80 + kb + 16);
            a8h1[3] = *(const uint32_t*)(p8h + (row0 + 24) * 80 + kb + 16);
            a8l0[0] = *(const uint32_t*)(p8l + row0 * 80 + kb);
            a8l0[1] = *(const uint32_t*)(p8l + (row0 + 8) * 80 + kb);
            a8l0[2] = *(const uint32_t*)(p8l + row0 * 80 + kb + 16);
            a8l0[3] = *(const uint32_t*)(p8l + (row0 + 8) * 80 + kb + 16);
            a8l1[0] = *(const uint32_t*)(p8l + (row0 + 16) * 80 + kb);
            a8l1[1] = *(const uint32_t*)(p8l + (row0 + 24) * 80 + kb);
            a8l1[2] = *(const uint32_t*)(p8l + (row0 + 16) * 80 + kb + 16);
            a8l1[3] = *(const uint32_t*)(p8l + (row0 + 24) * 80 + kb + 16);
#pragma unroll
            for (int ni = 0; ni < 4; ni++) {
                uint2 bba = sBbf[(((wn + ni) * 4) + 2 * ks32) * 32 + lane];
                uint2 bbb = sBbf[(((wn + ni) * 4) + 2 * ks32 + 1) * 32 + lane];
                uint4 b8 = sB8v[(((wn + ni) * 2) + ks32) * 32 + lane];
                mma16(acc[0][ni], ahA0, bba.x, bba.y);
                mma16(acc[1][ni], ahA1, bba.x, bba.y);
                mma16(acc[0][ni], ahB0, bbb.x, bbb.y);
                mma16(acc[1][ni], ahB1, bbb.x, bbb.y);
                mma32f8(accc[0][ni], a8l0, b8.x, b8.y);   // al*256 . bh
                mma32f8(accc[1][ni], a8l1, b8.x, b8.y);
                mma32f8(accc[0][ni], a8h0, b8.z, b8.w);   // ah . bl*256
                mma32f8(accc[1][ni], a8h1, b8.z, b8.w);
            }
        }
        __syncthreads();
    }
    // epilogue: row m = b*256+t -> out [t][b][GV]
#pragma unroll
    for (int mi = 0; mi < 2; mi++) {
#pragma unroll
        for (int half = 0; half < 2; half++) {
            int row = m0 + wm + mi * 16 + r + half * 8;
            int b = row >> 8, t = row & 255;
            float* orow = out + ((size_t)t * BSZ + b) * GV;
#pragma unroll
            for (int ni = 0; ni < 4; ni++) {
                int col = (n0blk + wn + ni) * 8 + 2 * cc;
                float2 bs = *(const float2*)&bias[col];
                float2 o;
                o.x = acc[mi][ni][half * 2 + 0] + accc[mi][ni][half * 2 + 0] * 0.00390625f + bs.x;
                o.y = acc[mi][ni][half * 2 + 1] + accc[mi][ni][half * 2 + 1] * 0.00390625f + bs.y;
                *(float2*)&orow[col] = o;
            }
        }
    }
}

// ---------------- recurrent scan (bf16x3, fused register epilogue) ----------------
#define SB_BYTES (96 * 1024)
#define SH_BYTES (32 * 528)
#define XB_OFF (SB_BYTES + 2 * SH_BYTES)          // 132096
#define XB_BYTES 12288                            // 32 rows x 96 floats
#define SCAN_SMEM (XB_OFF + 2 * XB_BYTES)         // 156672
__global__ void __launch_bounds__(256, 1) scan_kernel(const uint4* __restrict__ fWf,
                                                      const uint4* __restrict__ fWr,
                                                      const float* __restrict__ bhf,
                                                      const float* __restrict__ bhr,
                                                      const float* __restrict__ xgF,
                                                      const float* __restrict__ xgR,
                                                      float* __restrict__ recF,
                                                      uint32_t* __restrict__ recHi,
                                                      uint8_t* __restrict__ recH8,
                                                      uint8_t* __restrict__ recL8,
                                                      int mode) {
    uint4* sB4 = (uint4*)smem_raw;
    char* sHhi = smem_raw + SB_BYTES;
    char* sHlo = sHhi + SH_BYTES;
    __shared__ float sbh[96];

    int tid = threadIdx.x;
    int w = tid >> 5, lane = tid & 31;
    int dir = blockIdx.x >> 6;
    int tile = blockIdx.x & 63;
    int bt = tile >> 3, jt = tile & 7;
    int b0 = bt * 32, j0 = jt * 32, C0 = jt * 96;
    int grp = (int)(blockIdx.x >> 3);
    unsigned* gcnt = &g_gcnt[grp * 32];
    volatile unsigned* ggen = &g_ggen[grp * 32];

    const uint4* fW = dir ? fWr : fWf;
    const float* bh = dir ? bhr : bhf;
    const float* xg = dir ? xgR : xgF;

    for (int idx = tid; idx < 12 * 16 * 32; idx += 256)
        sB4[idx] = fW[(size_t)jt * (12 * 16 * 32) + idx];
    if (tid < 96) sbh[tid] = bh[C0 + tid];

    int wx = w & 3, my = (w >> 2) * 16;
    int r = lane >> 2, cc = lane & 3;
    int rl = lane & 15, kh = (lane >> 4) * 16;
    uint32_t sbase = smem_u32(smem_raw);
    uint32_t aH0 = sbase + SB_BYTES + (my + rl) * 528 + kh;
    uint32_t aL0 = aH0 + SH_BYTES;
    int jl0 = wx * 8 + 2 * cc;
    int wj = (j0 + jl0) >> 1;

    {
        int t0 = dir ? (TLEN - 1) : 0;
        const float* src = xg + ((size_t)t0 * BSZ + b0) * GV + C0;
        for (int i = tid; i < 768; i += 256) {
            int row = i / 24, q = i % 24;
            cpa16(sbase + XB_OFF + row * 384 + q * 16, &src[(size_t)row * GV + q * 4]);
        }
        CP_COMMIT();
    }

    int cur = 0;
    for (int step = 0; step < TLEN; step++) {
        int t = dir ? (TLEN - 1 - step) : step;
        const uint32_t* hsh = g_hshi[cur][dir];
        const uint32_t* hsl = g_hslo[cur][dir];
        uint32_t* hshN = g_hshi[cur ^ 1][dir];
        uint32_t* hslN = g_hslo[cur ^ 1][dir];

        {
            int sn = step + 1 < TLEN ? step + 1 : TLEN - 1;
            int tn = dir ? (TLEN - 1 - sn) : sn;
            const float* src = xg + ((size_t)tn * BSZ + b0) * GV + C0;
            uint32_t dstb = sbase + XB_OFF + ((step + 1) & 1) * XB_BYTES;
            for (int i = tid; i < 768; i += 256) {
                int row = i / 24, q = i % 24;
                cpa16(dstb + row * 384 + q * 16, &src[(size_t)row * GV + q * 4]);
            }
            CP_COMMIT();
        }

        for (int idx = tid; idx < 2048; idx += 256) {
            int half = idx >> 10;
            int row = (idx >> 5) & 31, q = idx & 31;
            const uint32_t* src = half ? hsl : hsh;
            uint4 v = *(const uint4*)&src[(size_t)(b0 + row) * 128 + q * 4];
            char* dst = half ? sHlo : sHhi;
            *(uint4*)(dst + row * 528 + q * 16) = v;
        }
        CP_WAIT1();
        __syncthreads();

        float acc[3][4] = {};
#pragma unroll 4
        for (int ks = 0; ks < 16; ks++) {
            uint32_t ah[4], al[4];
            ldm4(ah, aH0 + ks * 32);
            ldm4(al, aL0 + ks * 32);
#pragma unroll
            for (int ni = 0; ni < 3; ni++) {
                uint4 bb = sB4[(((wx + ni * 4)) * 16 + ks) * 32 + lane];
                mma16(acc[ni], ah, bb.x, bb.y);
                mma16(acc[ni], al, bb.x, bb.y);
                mma16(acc[ni], ah, bb.z, bb.w);
            }
        }

        const float* xb = (const float*)(smem_raw + XB_OFF + (step & 1) * XB_BYTES);
        float2 br = *(const float2*)&sbh[jl0];
        float2 bz = *(const float2*)&sbh[32 + jl0];
        float2 bn = *(const float2*)&sbh[64 + jl0];
        float2 rec_val[2];
        uint32_t rec_hw[2];
        int rows[2];
#pragma unroll
        for (int mi = 0; mi < 2; mi++) {
            int rl2 = my + r + mi * 8;
            int row = b0 + rl2;
            rows[mi] = row;
            const float* xrow = xb + rl2 * 96;
            float2 x_r = *(const float2*)&xrow[jl0];
            float2 x_z = *(const float2*)&xrow[32 + jl0];
            float2 x_n = *(const float2*)&xrow[64 + jl0];
            uint32_t hwo = *(const uint32_t*)(sHhi + rl2 * 528 + (j0 + jl0) * 2);
            uint32_t lwo = *(const uint32_t*)(sHlo + rl2 * 528 + (j0 + jl0) * 2);
            float ho0 = __uint_as_float(hwo << 16) + __uint_as_float(lwo << 16);
            float ho1 = __uint_as_float(hwo & 0xFFFF0000u) + __uint_as_float(lwo & 0xFFFF0000u);
            float hr0 = acc[0][mi * 2 + 0] + br.x;
            float hz0 = acc[1][mi * 2 + 0] + bz.x;
            float hn0 = acc[2][mi * 2 + 0] + bn.x;
            float rg0 = sigm(x_r.x + hr0);
            float zg0 = sigm(x_z.x + hz0);
            float ng0 = 2.0f * sigm(2.0f * (x_n.x + rg0 * hn0)) - 1.0f;
            float hv0 = (1.0f - zg0) * ng0 + zg0 * ho0;
            float hr1 = acc[0][mi * 2 + 1] + br.y;
            float hz1 = acc[1][mi * 2 + 1] + bz.y;
            float hn1 = acc[2][mi * 2 + 1] + bn.y;
            float rg1 = sigm(x_r.y + hr1);
            float zg1 = sigm(x_z.y + hz1);
            float ng1 = 2.0f * sigm(2.0f * (x_n.y + rg1 * hn1)) - 1.0f;
            float hv1 = (1.0f - zg1) * ng1 + zg1 * ho1;
            uint32_t hw, lw;
            split2pack(hv0, hv1, hw, lw);
            hshN[(size_t)row * 128 + wj] = hw;
            hslN[(size_t)row * 128 + wj] = lw;
            rec_val[mi] = make_float2(hv0, hv1);
            rec_hw[mi] = hw;
        }
        __syncthreads();

        unsigned mygen = 0;
        int flipped = 0;
        if (tid == 0) {
            mygen = *ggen;
            __threadfence();
            unsigned tt = atomicAdd(gcnt, 1u);
            if (tt == 7u) {
                *gcnt = 0u;
                __threadfence();
                *ggen = mygen + 1u;
                flipped = 1;
            }
        }
#pragma unroll
        for (int mi = 0; mi < 2; mi++) {
            if (mode) {
                *(float2*)&recF[((size_t)rows[mi] * TLEN + t) * H2V + dir * HV + j0 + jl0] =
                    rec_val[mi];
            } else {
                size_t o = ((size_t)rows[mi] * TLEN + t) * 256 + dir * 128 + wj;
                recHi[o] = rec_hw[mi];
                float hv0 = rec_val[mi].x, hv1 = rec_val[mi].y;
                uint32_t hw = rec_hw[mi];
                float hi0f = __uint_as_float(hw << 16);
                float hi1f = __uint_as_float(hw & 0xFFFF0000u);
                size_t ob = ((size_t)rows[mi] * TLEN + t) * 512 + dir * 256 + j0 + jl0;
                *(uint16_t*)&recH8[ob] = e4m3x2(hv1, hv0);
                *(uint16_t*)&recL8[ob] = e4m3x2((hv1 - hi1f) * 256.0f, (hv0 - hi0f) * 256.0f);
            }
        }
        if (tid == 0 && !flipped) {
            while (*ggen == mygen) { __nanosleep(20); }
        }
        if (tid == 0) __threadfence();
        __syncthreads();
        cur ^= 1;
    }
}

// ---------------- attention + output ----------------
__global__ void __launch_bounds__(256) attention_kernel(const float* __restrict__ rec2,
                                                        float* __restrict__ out) {
    __shared__ float smerged[512];
    __shared__ float sc[256];
    __shared__ float red[8];
    __shared__ float bcast;
    int b = blockIdx.x, tid = threadIdx.x;
    const float* base = rec2 + (size_t)b * (TLEN * H2V);

    smerged[tid] = base[255 * H2V + tid];
    smerged[256 + tid] = base[256 + tid];
    __syncthreads();

    int lane = tid & 31, wid = tid >> 5;
    for (int t = wid; t < TLEN; t += 8) {
        const float* row = base + (size_t)t * H2V;
        float s = 0.0f;
        for (int h = lane; h < H2V; h += 32) s += row[h] * smerged[h];
#pragma unroll
        for (int o = 16; o; o >>= 1) s += __shfl_xor_sync(0xffffffffu, s, o);
        if (lane == 0) sc[t] = s;
    }
    __syncthreads();

    float v = sc[tid];
    float m = v;
#pragma unroll
    for (int o = 16; o; o >>= 1) m = fmaxf(m, __shfl_xor_sync(0xffffffffu, m, o));
    if (lane == 0) red[wid] = m;
    __syncthreads();
    if (tid == 0) {
        float mm = red[0];
        for (int i = 1; i < 8; i++) mm = fmaxf(mm, red[i]);
        bcast = mm;
    }
    __syncthreads();
    m = bcast;
    float e = expf(v - m);
    float s = e;
#pragma unroll
    for (int o = 16; o; o >>= 1) s += __shfl_xor_sync(0xffffffffu, s, o);
    if (lane == 0) red[wid] = s;
    __syncthreads();
    if (tid == 0) {
        float ss = 0.0f;
        for (int i = 0; i < 8; i++) ss += red[i];
        bcast = ss;
    }
    __syncthreads();
    float wgt = e / bcast;
    sc[tid] = wgt;
    __syncthreads();

    float a0 = 0.0f, a1 = 0.0f;
    for (int t = 0; t < TLEN; t++) {
        float wt = sc[t];
        a0 += wt * base[(size_t)t * H2V + tid];
        a1 += wt * base[(size_t)t * H2V + 256 + tid];
    }
    float* ob = out + (size_t)b * 1024;
    ob[tid] = a0;
    ob[256 + tid] = a1;
    ob[512 + tid] = base[255 * H2V + tid];
    ob[768 + tid] = base[255 * H2V + 256 + tid];
}

// ---------------- host launcher ----------------
extern "C" void kernel_launch(void* const* d_in, const int* in_sizes, int n_in,
                              void* d_out, int out_size) {
    (void)in_sizes; (void)n_in; (void)out_size;
    const float* input = (const float*)d_in[0];
    const float* wih1f = (const float*)d_in[1];
    const float* whh1f = (const float*)d_in[2];
    const float* bih1f = (const float*)d_in[3];
    const float* bhh1f = (const float*)d_in[4];
    const float* wih1r = (const float*)d_in[5];
    const float* whh1r = (const float*)d_in[6];
    const float* bih1r = (const float*)d_in[7];
    const float* bhh1r = (const float*)d_in[8];
    const float* wih2f = (const float*)d_in[9];
    const float* whh2f = (const float*)d_in[10];
    const float* bih2f = (const float*)d_in[11];
    const float* bhh2f = (const float*)d_in[12];
    const float* wih2r = (const float*)d_in[13];
    const float* whh2r = (const float*)d_in[14];
    const float* bih2r = (const float*)d_in[15];
    const float* bhh2r = (const float*)d_in[16];

    uint4 *fH1f, *fH1r, *fH2f, *fH2r;
    uint2 *fWbf1f, *fWbf1r, *fWbf2f, *fWbf2r;
    uint4 *fW8_1f, *fW8_1r, *fW8_2f, *fW8_2r;
    float *bihP, *bhhP, *xgf, *xgr, *rec2;
    uint32_t *xinhi, *r1hi;
    uint8_t *xh8, *xl8, *r1h8, *r1l8;
    cudaGetSymbolAddress((void**)&fH1f, g_fH1f);
    cudaGetSymbolAddress((void**)&fH1r, g_fH1r);
    cudaGetSymbolAddress((void**)&fH2f, g_fH2f);
    cudaGetSymbolAddress((void**)&fH2r, g_fH2r);
    cudaGetSymbolAddress((void**)&fWbf1f, g_fWbf1f);
    cudaGetSymbolAddress((void**)&fWbf1r, g_fWbf1r);
    cudaGetSymbolAddress((void**)&fWbf2f, g_fWbf2f);
    cudaGetSymbolAddress((void**)&fWbf2r, g_fWbf2r);
    cudaGetSymbolAddress((void**)&fW8_1f, g_fW8_1f);
    cudaGetSymbolAddress((void**)&fW8_1r, g_fW8_1r);
    cudaGetSymbolAddress((void**)&fW8_2f, g_fW8_2f);
    cudaGetSymbolAddress((void**)&fW8_2r, g_fW8_2r);
    cudaGetSymbolAddress((void**)&bihP, g_bihP);
    cudaGetSymbolAddress((void**)&bhhP, g_bhhP);
    cudaGetSymbolAddress((void**)&xgf, g_xgf);
    cudaGetSymbolAddress((void**)&xgr, g_xgr);
    cudaGetSymbolAddress((void**)&rec2, g_rec2);
    cudaGetSymbolAddress((void**)&xinhi, g_xinhi);
    cudaGetSymbolAddress((void**)&xh8, g_xh8);
    cudaGetSymbolAddress((void**)&xl8, g_xl8);
    cudaGetSymbolAddress((void**)&r1hi, g_r1hi);
    cudaGetSymbolAddress((void**)&r1h8, g_r1h8);
    cudaGetSymbolAddress((void**)&r1l8, g_r1l8);

    split_input<<<2048, 256>>>(input, xinhi, xh8, xl8, BSZ * TLEN * (NINV / 2));
    pack_fragbf<<<96, 256>>>(fWbf1f, wih1f, NINV);
    pack_fragbf<<<96, 256>>>(fWbf1r, wih1r, NINV);
    pack_fragbf<<<192, 256>>>(fWbf2f, wih2f, H2V);
    pack_fragbf<<<192, 256>>>(fWbf2r, wih2r, H2V);
    pack_frag8<<<48, 256>>>(fW8_1f, wih1f, NINV);
    pack_frag8<<<48, 256>>>(fW8_1r, wih1r, NINV);
    pack_frag8<<<192, 256>>>(fW8_2f, wih2f, H2V);
    pack_frag8<<<192, 256>>>(fW8_2r, wih2r, H2V);
    pack_frag<<<128, 256>>>(fH1f, whh1f, HV);
    pack_frag<<<128, 256>>>(fH1r, whh1r, HV);
    pack_frag<<<128, 256>>>(fH2f, whh2f, HV);
    pack_frag<<<128, 256>>>(fH2r, whh2r, HV);
    pack_b<<<1, 768>>>(bihP + 0 * GV, bih1f);
    pack_b<<<1, 768>>>(bihP + 1 * GV, bih1r);
    pack_b<<<1, 768>>>(bihP + 2 * GV, bih2f);
    pack_b<<<1, 768>>>(bihP + 3 * GV, bih2r);
    pack_b<<<1, 768>>>(bhhP + 0 * GV, bhh1f);
    pack_b<<<1, 768>>>(bhhP + 1 * GV, bhh1r);
    pack_b<<<1, 768>>>(bhhP + 2 * GV, bhh2f);
    pack_b<<<1, 768>>>(bhhP + 3 * GV, bhh2r);

    cudaFuncSetAttribute(xg_mma<64>, cudaFuncAttributeMaxDynamicSharedMemorySize, XG_SMEM);
    cudaFuncSetAttribute(xg_mma<256>, cudaFuncAttributeMaxDynamicSharedMemorySize, XG_SMEM);
    cudaFuncSetAttribute(scan_kernel, cudaFuncAttributeMaxDynamicSharedMemorySize, SCAN_SMEM);

    // Layer 1
    xg_mma<64><<<dim3(12, 1024), 128, XG_SMEM>>>(xinhi, xh8, xl8, fWbf1f, fW8_1f,
                                                 bihP + 0 * GV, xgf);
    xg_mma<64><<<dim3(12, 1024), 128, XG_SMEM>>>(xinhi, xh8, xl8, fWbf1r, fW8_1r,
                                                 bihP + 1 * GV, xgr);
    zero_h<<<256, 256>>>();
    scan_kernel<<<128, 256, SCAN_SMEM>>>(fH1f, fH1r, bhhP + 0 * GV, bhhP + 1 * GV,
                                         xgf, xgr, nullptr, r1hi, r1h8, r1l8, 0);
    // Layer 2
    xg_mma<256><<<dim3(12, 1024), 128, XG_SMEM>>>(r1hi, r1h8, r1l8, fWbf2f, fW8_2f,
                                                  bihP + 2 * GV, xgf);
    xg_mma<256><<<dim3(12, 1024), 128, XG_SMEM>>>(r1hi, r1h8, r1l8, fWbf2r, fW8_2r,
                                                  bihP + 3 * GV, xgr);
    zero_h<<<256, 256>>>();
    scan_kernel<<<128, 256, SCAN_SMEM>>>(fH2f, fH2r, bhhP + 2 * GV, bhhP + 3 * GV,
                                         xgf, xgr, rec2, nullptr, nullptr, nullptr, 1);
    // Attention + output
    attention_kernel<<<256, 256>>>(rec2, (float*)d_out);
}